// round 5
// baseline (speedup 1.0000x reference)
#include <cuda_runtime.h>
#include <cstdint>

// weight_quantize_fn: out = alpha * SF * q_kept * sign, with group-of-16 term budget.
// R5: reduce1 rebuilt in quant's execution shape — 8192 one-shot CTAs, 4 coalesced
//     float4 loads/thread, warp-shuffle double reduction, last-block finalize.
//     (R4 showed long-running 8-deep-unroll CTAs serialize LDGs on register recycle;
//      the memory system gives 5.4-6.6 TB/s to many-short-CTA shapes.)

#define RT 256
#define RVPT 4                  // float4 per thread in reduce
#define RCHUNK (RT * RVPT)      // 1024 float4 = 16KB per block
#define MAXB 16384
#define QT 256

__device__ double g_psum[MAXB];
__device__ double g_psq[MAXB];
__device__ float  g_consts[4];   // [0]=scale=1/(std*alpha), [1]=bias=-mean*scale, [2]=C=SF*alpha
__device__ unsigned g_count;     // zero-init; wraps back to 0 every launch (graph-replay safe)

typedef unsigned long long u64;

// ---- packed f32x2 helpers (Blackwell) ----
__device__ __forceinline__ u64 pk2(float lo, float hi) {
    u64 r; asm("mov.b64 %0, {%1, %2};" : "=l"(r) : "f"(lo), "f"(hi)); return r;
}
__device__ __forceinline__ void upk2(u64 v, float& lo, float& hi) {
    asm("mov.b64 {%0, %1}, %2;" : "=f"(lo), "=f"(hi) : "l"(v));
}
__device__ __forceinline__ u64 ffma2(u64 a, u64 b, u64 c) {
    u64 d; asm("fma.rn.f32x2 %0, %1, %2, %3;" : "=l"(d) : "l"(a), "l"(b), "l"(c)); return d;
}
__device__ __forceinline__ u64 fadd2(u64 a, u64 b) {
    u64 d; asm("add.rn.f32x2 %0, %1, %2;" : "=l"(d) : "l"(a), "l"(b)); return d;
}
__device__ __forceinline__ u64 fmul2(u64 a, u64 b) {
    u64 d; asm("mul.rn.f32x2 %0, %1, %2;" : "=l"(d) : "l"(a), "l"(b)); return d;
}
__device__ __forceinline__ void stcs4(float4* p, float4 v) {
    asm volatile("st.global.cs.v4.f32 [%0], {%1, %2, %3, %4};"
                 :: "l"(p), "f"(v.x), "f"(v.y), "f"(v.z), "f"(v.w) : "memory");
}

// ---- pass 1: one-shot CTAs, 4 coalesced float4/thread, fused finalize ----
__global__ void __launch_bounds__(RT) reduce1(const float4* __restrict__ x,
                                              const float* __restrict__ alpha_p,
                                              int nvec, long long n) {
    __shared__ double ssw[RT / 32], sqw[RT / 32];
    __shared__ bool is_last;

    int base = blockIdx.x * RCHUNK + threadIdx.x;
    float s0 = 0.f, s1 = 0.f, s2 = 0.f, s3 = 0.f;
    float q0 = 0.f, q1 = 0.f, q2 = 0.f, q3 = 0.f;

    if (base + 3 * RT < nvec) {
        float4 a = x[base];
        float4 b = x[base + RT];
        float4 c = x[base + 2 * RT];
        float4 d = x[base + 3 * RT];
        s0 = (a.x + a.y) + (a.z + a.w);
        q0 = (a.x * a.x + a.y * a.y) + (a.z * a.z + a.w * a.w);
        s1 = (b.x + b.y) + (b.z + b.w);
        q1 = (b.x * b.x + b.y * b.y) + (b.z * b.z + b.w * b.w);
        s2 = (c.x + c.y) + (c.z + c.w);
        q2 = (c.x * c.x + c.y * c.y) + (c.z * c.z + c.w * c.w);
        s3 = (d.x + d.y) + (d.z + d.w);
        q3 = (d.x * d.x + d.y * d.y) + (d.z * d.z + d.w * d.w);
    } else {
#pragma unroll
        for (int k = 0; k < RVPT; k++) {
            int i = base + k * RT;
            if (i < nvec) {
                float4 a = x[i];
                s0 += (a.x + a.y) + (a.z + a.w);
                q0 += (a.x * a.x + a.y * a.y) + (a.z * a.z + a.w * a.w);
            }
        }
    }

    double s = ((double)s0 + (double)s1) + ((double)s2 + (double)s3);
    double q = ((double)q0 + (double)q1) + ((double)q2 + (double)q3);
#pragma unroll
    for (int o = 16; o > 0; o >>= 1) {
        s += __shfl_down_sync(0xffffffffu, s, o);
        q += __shfl_down_sync(0xffffffffu, q, o);
    }
    int wid = threadIdx.x >> 5, lane = threadIdx.x & 31;
    if (lane == 0) { ssw[wid] = s; sqw[wid] = q; }
    __syncthreads();
    if (threadIdx.x == 0) {
        double ts = 0.0, tq = 0.0;
#pragma unroll
        for (int i = 0; i < RT / 32; i++) { ts += ssw[i]; tq += sqw[i]; }
        g_psum[blockIdx.x] = ts;
        g_psq[blockIdx.x] = tq;
    }

    // Last-block finalize (deterministic order).
    __threadfence();
    if (threadIdx.x == 0) {
        unsigned c = atomicInc(&g_count, gridDim.x - 1);   // wraps to 0 for next launch
        is_last = (c == gridDim.x - 1);
    }
    __syncthreads();
    if (is_last) {
        double ts = 0.0, tq = 0.0;
        for (int i = threadIdx.x; i < gridDim.x; i += RT) { ts += g_psum[i]; tq += g_psq[i]; }
#pragma unroll
        for (int o = 16; o > 0; o >>= 1) {
            ts += __shfl_down_sync(0xffffffffu, ts, o);
            tq += __shfl_down_sync(0xffffffffu, tq, o);
        }
        if (lane == 0) { ssw[wid] = ts; sqw[wid] = tq; }
        __syncthreads();
        if (threadIdx.x == 0) {
            double fs = 0.0, fq = 0.0;
#pragma unroll
            for (int i = 0; i < RT / 32; i++) { fs += ssw[i]; fq += sqw[i]; }
            double N = (double)n;
            double mean = fs / N;
            double var  = (fq - N * mean * mean) / (N - 1.0);   // unbiased (ddof=1)
            double stdv = sqrt(var);
            double alpha = (double)(*alpha_p);
            double inv = 1.0 / (stdv * alpha);
            g_consts[0] = (float)inv;
            g_consts[1] = (float)(-mean * inv);
            g_consts[2] = (float)((double)(1.0f / 7.0f) * alpha);  // SF (fp32 1/7) * alpha
        }
    }
}

// ---- pass 2: quantize. One float4 per thread; 4-lane clusters own one group of 16. ----
__global__ void __launch_bounds__(QT) quant(const float4* __restrict__ xv,
                                            float4* __restrict__ ov,
                                            const int* __restrict__ ntp, int nvec) {
    // Reverse block order: consume the L2-resident tail left by reduce1 first.
    int rb = gridDim.x - 1 - blockIdx.x;
    int idx = rb * blockDim.x + threadIdx.x;
    if (idx >= nvec) return;

    float scale = g_consts[0], bias = g_consts[1], C = g_consts[2];
    const float MAGIC = 8388608.0f;               // 2^23: RN add == round-half-even to int
    u64 s2 = pk2(scale, scale);
    u64 b2 = pk2(bias, bias);
    u64 seven2  = pk2(7.0f, 7.0f);
    u64 magic2  = pk2(MAGIC, MAGIC);
    u64 nmagic2 = pk2(-MAGIC, -MAGIC);
    u64 C2 = pk2(C, C);

    float4 v = xv[idx];                           // fully coalesced
    float X[4] = {v.x, v.y, v.z, v.w};

    float t[4], f[4];
#pragma unroll
    for (int p = 0; p < 2; p++) {
        u64 t2 = ffma2(pk2(X[2 * p], X[2 * p + 1]), s2, b2);    // t = x*scale + bias
        upk2(t2, t[2 * p], t[2 * p + 1]);
        float al = fminf(fabsf(t[2 * p]), 1.0f);                // |clip(t)| — FMNMX with |src|
        float ah = fminf(fabsf(t[2 * p + 1]), 1.0f);
        u64 f2 = ffma2(pk2(al, ah), seven2, magic2);            // f = 2^23 + q (round-half-even)
        upk2(f2, f[2 * p], f[2 * p + 1]);
    }

    // Group sum of q over the 16 elements owned by this 4-lane cluster.
    int qs = __float_as_int(f[0]) + __float_as_int(f[1]) +
             __float_as_int(f[2]) + __float_as_int(f[3]);
    qs += __shfl_xor_sync(0xffffffffu, qs, 1);
    qs += __shfl_xor_sync(0xffffffffu, qs, 2);

    int budget = __ldg(ntp) * 16;                 // num_terms * group_size

    float4 w;
    float* r = &w.x;
    // popc(q) <= (q+1)/2 for q in [0,7]  =>  sum(q) <= 2*budget-16 guarantees terms <= budget.
    if ((qs & 0xff) <= 2 * budget - 16) {
        // Fast path: every term kept -> qk == q.
#pragma unroll
        for (int p = 0; p < 2; p++) {
            u64 qf2 = fadd2(pk2(f[2 * p], f[2 * p + 1]), nmagic2);  // exact: qf = q as float
            u64 o2  = fmul2(qf2, C2);                               // |out| = q*SF*alpha
            float ol, oh; upk2(o2, ol, oh);
            r[2 * p]     = __int_as_float(__float_as_int(ol) | (__float_as_int(t[2 * p])     & 0x80000000));
            r[2 * p + 1] = __int_as_float(__float_as_int(oh) | (__float_as_int(t[2 * p + 1]) & 0x80000000));
        }
    } else {
        // Exact path (rare): stable-descending-sort semantics.
        int lane = threadIdx.x & 31;
        unsigned cmask = 0xFu << (lane & ~3);     // the 4 lanes of this cluster
        int pos = (lane & 3) * 4;                 // this lane's element offset in the group
        int m1 = 0, m2 = 0, m4 = 0;
#pragma unroll
        for (int k = 0; k < 4; k++) {
            int q = __float_as_int(f[k]) & 7;
            m1 |= (q & 1) << (pos + k);
            m2 |= ((q >> 1) & 1) << (pos + k);
            m4 |= ((q >> 2) & 1) << (pos + k);
        }
        m1 |= __shfl_xor_sync(cmask, m1, 1);  m1 |= __shfl_xor_sync(cmask, m1, 2);
        m2 |= __shfl_xor_sync(cmask, m2, 1);  m2 |= __shfl_xor_sync(cmask, m2, 2);
        m4 |= __shfl_xor_sync(cmask, m4, 1);  m4 |= __shfl_xor_sync(cmask, m4, 2);
        int c4 = min(__popc(m4), budget);
        int rem = budget - c4;
        int c2 = min(__popc(m2), rem); rem -= c2;
        int c1 = min(__popc(m1), rem);
        if (c1 < 0) c1 = 0;
#pragma unroll
        for (int k = 0; k < 4; k++) {
            int i16 = pos + k;
            int below = (1 << i16) - 1;
            int k4 = ((m4 >> i16) & 1) & ((__popc(m4 & below) < c4) ? 1 : 0);
            int k2 = ((m2 >> i16) & 1) & ((__popc(m2 & below) < c2) ? 1 : 0);
            int k1 = ((m1 >> i16) & 1) & ((__popc(m1 & below) < c1) ? 1 : 0);
            int kept = (k4 << 2) | (k2 << 1) | k1;
            float o = (float)kept * C;
            r[k] = __int_as_float(__float_as_int(o) | (__float_as_int(t[k]) & 0x80000000));
        }
    }

    stcs4(&ov[idx], w);                           // coalesced streaming store
}

extern "C" void kernel_launch(void* const* d_in, const int* in_sizes, int n_in,
                              void* d_out, int out_size) {
    const float* w     = (const float*)d_in[0];
    const float* alpha = (const float*)d_in[1];
    const int*   nt    = (const int*)d_in[2];
    int n = in_sizes[0];
    int nvec = n / 4;

    int nb = (nvec + RCHUNK - 1) / RCHUNK;       // 8192 for 4096x8192
    if (nb > MAXB) nb = MAXB;                    // (33.5M elems -> 8192, always fits)

    reduce1<<<nb, RT>>>((const float4*)w, alpha, nvec, (long long)n);
    int qb = (nvec + QT - 1) / QT;
    quant<<<qb, QT>>>((const float4*)w, (float4*)d_out, nt, nvec);
}

// round 6
// speedup vs baseline: 1.9410x; 1.9410x over previous
#include <cuda_runtime.h>
#include <cstdint>

// weight_quantize_fn: out = alpha * SF * q_kept * sign, with group-of-16 term budget.
// R6: revert to R2 two-kernel structure (fused finalize at scale = same-address
//     atomic serialization disaster). New lever: ld.global.cs streaming loads in
//     reduce1 — all prior reduce variants used default cached LDG and capped at
//     ~3500 B/cyc while quant sits at the ~6300 B/cyc LTS wall.

#define RED_BLOCKS 1184
#define RED_THREADS 256
#define QT 256

__device__ double g_psum[RED_BLOCKS];
__device__ double g_psq[RED_BLOCKS];
__device__ float  g_consts[4];   // [0]=scale=1/(std*alpha), [1]=bias=-mean*scale, [2]=C=SF*alpha

typedef unsigned long long u64;

// ---- packed f32x2 helpers (Blackwell) ----
__device__ __forceinline__ u64 pk2(float lo, float hi) {
    u64 r; asm("mov.b64 %0, {%1, %2};" : "=l"(r) : "f"(lo), "f"(hi)); return r;
}
__device__ __forceinline__ void upk2(u64 v, float& lo, float& hi) {
    asm("mov.b64 {%0, %1}, %2;" : "=f"(lo), "=f"(hi) : "l"(v));
}
__device__ __forceinline__ u64 ffma2(u64 a, u64 b, u64 c) {
    u64 d; asm("fma.rn.f32x2 %0, %1, %2, %3;" : "=l"(d) : "l"(a), "l"(b), "l"(c)); return d;
}
__device__ __forceinline__ u64 fadd2(u64 a, u64 b) {
    u64 d; asm("add.rn.f32x2 %0, %1, %2;" : "=l"(d) : "l"(a), "l"(b)); return d;
}
__device__ __forceinline__ u64 fmul2(u64 a, u64 b) {
    u64 d; asm("mul.rn.f32x2 %0, %1, %2;" : "=l"(d) : "l"(a), "l"(b)); return d;
}
__device__ __forceinline__ void stcs4(float4* p, float4 v) {
    asm volatile("st.global.cs.v4.f32 [%0], {%1, %2, %3, %4};"
                 :: "l"(p), "f"(v.x), "f"(v.y), "f"(v.z), "f"(v.w) : "memory");
}
__device__ __forceinline__ float4 ldcs4(const float4* p) {
    float4 v;
    asm volatile("ld.global.cs.v4.f32 {%0, %1, %2, %3}, [%4];"
                 : "=f"(v.x), "=f"(v.y), "=f"(v.z), "=f"(v.w) : "l"(p));
    return v;
}

// ---- pass 1: per-block partial sum / sumsq; fp32 hot loop, streaming loads ----
__global__ void __launch_bounds__(RED_THREADS) reduce1(const float4* __restrict__ x, int nvec) {
    __shared__ double ss[RED_THREADS], sq[RED_THREADS];
    float s0 = 0.f, s1 = 0.f, q0 = 0.f, q1 = 0.f;   // 2 independent chains
    int stride = gridDim.x * blockDim.x;
    int i = blockIdx.x * blockDim.x + threadIdx.x;
    for (; i + stride < nvec; i += 2 * stride) {
        float4 a = ldcs4(x + i);
        float4 b = ldcs4(x + i + stride);
        s0 += (a.x + a.y) + (a.z + a.w);
        q0 += (a.x * a.x + a.y * a.y) + (a.z * a.z + a.w * a.w);
        s1 += (b.x + b.y) + (b.z + b.w);
        q1 += (b.x * b.x + b.y * b.y) + (b.z * b.z + b.w * b.w);
    }
    if (i < nvec) {
        float4 a = ldcs4(x + i);
        s0 += (a.x + a.y) + (a.z + a.w);
        q0 += (a.x * a.x + a.y * a.y) + (a.z * a.z + a.w * a.w);
    }
    ss[threadIdx.x] = (double)s0 + (double)s1;
    sq[threadIdx.x] = (double)q0 + (double)q1;
    __syncthreads();
    for (int o = RED_THREADS >> 1; o > 0; o >>= 1) {
        if (threadIdx.x < o) {
            ss[threadIdx.x] += ss[threadIdx.x + o];
            sq[threadIdx.x] += sq[threadIdx.x + o];
        }
        __syncthreads();
    }
    if (threadIdx.x == 0) { g_psum[blockIdx.x] = ss[0]; g_psq[blockIdx.x] = sq[0]; }
}

// ---- pass 2: finalize mean/std (ddof=1) and fold constants ----
__global__ void reduce2(const float* __restrict__ alpha_p, long long n) {
    __shared__ double ss[256], sq[256];
    double s = 0.0, q = 0.0;
    for (int i = threadIdx.x; i < RED_BLOCKS; i += 256) { s += g_psum[i]; q += g_psq[i]; }
    ss[threadIdx.x] = s; sq[threadIdx.x] = q;
    __syncthreads();
    for (int o = 128; o > 0; o >>= 1) {
        if (threadIdx.x < o) {
            ss[threadIdx.x] += ss[threadIdx.x + o];
            sq[threadIdx.x] += sq[threadIdx.x + o];
        }
        __syncthreads();
    }
    if (threadIdx.x == 0) {
        double N = (double)n;
        double mean = ss[0] / N;
        double var  = (sq[0] - N * mean * mean) / (N - 1.0);   // unbiased (ddof=1)
        double stdv = sqrt(var);
        double alpha = (double)(*alpha_p);
        double inv = 1.0 / (stdv * alpha);
        g_consts[0] = (float)inv;
        g_consts[1] = (float)(-mean * inv);
        g_consts[2] = (float)((double)(1.0f / 7.0f) * alpha);  // SF (fp32 1/7) * alpha
    }
}

// ---- pass 3: quantize. One float4 per thread; 4-lane clusters own one group of 16. ----
__global__ void __launch_bounds__(QT) quant(const float4* __restrict__ xv,
                                            float4* __restrict__ ov,
                                            const int* __restrict__ ntp, int nvec) {
    // Reverse block order: consume the L2-resident tail left by reduce1 first.
    int rb = gridDim.x - 1 - blockIdx.x;
    int idx = rb * blockDim.x + threadIdx.x;
    if (idx >= nvec) return;

    float scale = g_consts[0], bias = g_consts[1], C = g_consts[2];
    const float MAGIC = 8388608.0f;               // 2^23: RN add == round-half-even to int
    u64 s2 = pk2(scale, scale);
    u64 b2 = pk2(bias, bias);
    u64 seven2  = pk2(7.0f, 7.0f);
    u64 magic2  = pk2(MAGIC, MAGIC);
    u64 nmagic2 = pk2(-MAGIC, -MAGIC);
    u64 C2 = pk2(C, C);

    float4 v = xv[idx];                           // fully coalesced
    float X[4] = {v.x, v.y, v.z, v.w};

    float t[4], f[4];
#pragma unroll
    for (int p = 0; p < 2; p++) {
        u64 t2 = ffma2(pk2(X[2 * p], X[2 * p + 1]), s2, b2);    // t = x*scale + bias
        upk2(t2, t[2 * p], t[2 * p + 1]);
        float al = fminf(fabsf(t[2 * p]), 1.0f);                // |clip(t)| — FMNMX with |src|
        float ah = fminf(fabsf(t[2 * p + 1]), 1.0f);
        u64 f2 = ffma2(pk2(al, ah), seven2, magic2);            // f = 2^23 + q (round-half-even)
        upk2(f2, f[2 * p], f[2 * p + 1]);
    }

    // Group sum of q over the 16 elements owned by this 4-lane cluster.
    int qs = __float_as_int(f[0]) + __float_as_int(f[1]) +
             __float_as_int(f[2]) + __float_as_int(f[3]);
    qs += __shfl_xor_sync(0xffffffffu, qs, 1);
    qs += __shfl_xor_sync(0xffffffffu, qs, 2);

    int budget = __ldg(ntp) * 16;                 // num_terms * group_size

    float4 w;
    float* r = &w.x;
    // popc(q) <= (q+1)/2 for q in [0,7]  =>  sum(q) <= 2*budget-16 guarantees terms <= budget.
    if ((qs & 0xff) <= 2 * budget - 16) {
        // Fast path: every term kept -> qk == q.
#pragma unroll
        for (int p = 0; p < 2; p++) {
            u64 qf2 = fadd2(pk2(f[2 * p], f[2 * p + 1]), nmagic2);  // exact: qf = q as float
            u64 o2  = fmul2(qf2, C2);                               // |out| = q*SF*alpha
            float ol, oh; upk2(o2, ol, oh);
            r[2 * p]     = __int_as_float(__float_as_int(ol) | (__float_as_int(t[2 * p])     & 0x80000000));
            r[2 * p + 1] = __int_as_float(__float_as_int(oh) | (__float_as_int(t[2 * p + 1]) & 0x80000000));
        }
    } else {
        // Exact path (rare): stable-descending-sort semantics.
        int lane = threadIdx.x & 31;
        unsigned cmask = 0xFu << (lane & ~3);     // the 4 lanes of this cluster
        int pos = (lane & 3) * 4;                 // this lane's element offset in the group
        int m1 = 0, m2 = 0, m4 = 0;
#pragma unroll
        for (int k = 0; k < 4; k++) {
            int q = __float_as_int(f[k]) & 7;
            m1 |= (q & 1) << (pos + k);
            m2 |= ((q >> 1) & 1) << (pos + k);
            m4 |= ((q >> 2) & 1) << (pos + k);
        }
        m1 |= __shfl_xor_sync(cmask, m1, 1);  m1 |= __shfl_xor_sync(cmask, m1, 2);
        m2 |= __shfl_xor_sync(cmask, m2, 1);  m2 |= __shfl_xor_sync(cmask, m2, 2);
        m4 |= __shfl_xor_sync(cmask, m4, 1);  m4 |= __shfl_xor_sync(cmask, m4, 2);
        int c4 = min(__popc(m4), budget);
        int rem = budget - c4;
        int c2 = min(__popc(m2), rem); rem -= c2;
        int c1 = min(__popc(m1), rem);
        if (c1 < 0) c1 = 0;
#pragma unroll
        for (int k = 0; k < 4; k++) {
            int i16 = pos + k;
            int below = (1 << i16) - 1;
            int k4 = ((m4 >> i16) & 1) & ((__popc(m4 & below) < c4) ? 1 : 0);
            int k2 = ((m2 >> i16) & 1) & ((__popc(m2 & below) < c2) ? 1 : 0);
            int k1 = ((m1 >> i16) & 1) & ((__popc(m1 & below) < c1) ? 1 : 0);
            int kept = (k4 << 2) | (k2 << 1) | k1;
            float o = (float)kept * C;
            r[k] = __int_as_float(__float_as_int(o) | (__float_as_int(t[k]) & 0x80000000));
        }
    }

    stcs4(&ov[idx], w);                           // coalesced streaming store
}

extern "C" void kernel_launch(void* const* d_in, const int* in_sizes, int n_in,
                              void* d_out, int out_size) {
    const float* w     = (const float*)d_in[0];
    const float* alpha = (const float*)d_in[1];
    const int*   nt    = (const int*)d_in[2];
    int n = in_sizes[0];
    int nvec = n / 4;

    reduce1<<<RED_BLOCKS, RED_THREADS>>>((const float4*)w, nvec);
    reduce2<<<1, 256>>>(alpha, (long long)n);
    int qb = (nvec + QT - 1) / QT;
    quant<<<qb, QT>>>((const float4*)w, (float4*)d_out, nt, nvec);
}

// round 7
// speedup vs baseline: 1.9425x; 1.0008x over previous
#include <cuda_runtime.h>
#include <cstdint>

// weight_quantize_fn: out = alpha * SF * q_kept * sign, with group-of-16 term budget.
// R7: reduction rebuilt in quant's EXACT execution shape (32768 one-shot CTAs,
//     1 float4/thread — the shape measured at 6.4 TB/s) with fp32 warp-shuffle
//     partials, NO atomics (R5's 8192 serialized atomicIncs were the regression),
//     and a 2-stage deterministic finalize over the 32768 float2 partials.

#define AT 256                  // reduceA block
#define MAXP 65536              // max partials (CTAs of reduceA)
#define NB2 64                  // reduceB blocks
#define QT 256

__device__ float2 g_part[MAXP];      // per-CTA (sum, sumsq) fp32 partials
__device__ double g_mid[2 * NB2];    // per-reduceB-block (sum, sumsq) doubles
__device__ float  g_consts[4];       // [0]=1/(std*alpha), [1]=-mean/(std*alpha), [2]=SF*alpha

typedef unsigned long long u64;

// ---- packed f32x2 helpers (Blackwell) ----
__device__ __forceinline__ u64 pk2(float lo, float hi) {
    u64 r; asm("mov.b64 %0, {%1, %2};" : "=l"(r) : "f"(lo), "f"(hi)); return r;
}
__device__ __forceinline__ void upk2(u64 v, float& lo, float& hi) {
    asm("mov.b64 {%0, %1}, %2;" : "=f"(lo), "=f"(hi) : "l"(v));
}
__device__ __forceinline__ u64 ffma2(u64 a, u64 b, u64 c) {
    u64 d; asm("fma.rn.f32x2 %0, %1, %2, %3;" : "=l"(d) : "l"(a), "l"(b), "l"(c)); return d;
}
__device__ __forceinline__ u64 fadd2(u64 a, u64 b) {
    u64 d; asm("add.rn.f32x2 %0, %1, %2;" : "=l"(d) : "l"(a), "l"(b)); return d;
}
__device__ __forceinline__ u64 fmul2(u64 a, u64 b) {
    u64 d; asm("mul.rn.f32x2 %0, %1, %2;" : "=l"(d) : "l"(a), "l"(b)); return d;
}
__device__ __forceinline__ void stcs4(float4* p, float4 v) {
    asm volatile("st.global.cs.v4.f32 [%0], {%1, %2, %3, %4};"
                 :: "l"(p), "f"(v.x), "f"(v.y), "f"(v.z), "f"(v.w) : "memory");
}

// ---- stage A: one-shot CTAs, 1 float4/thread, fp32 partial per CTA ----
__global__ void __launch_bounds__(AT) reduceA(const float4* __restrict__ x, int nvec) {
    int idx = blockIdx.x * AT + threadIdx.x;
    float s = 0.f, q = 0.f;
    if (idx < nvec) {
        float4 a = x[idx];
        s = (a.x + a.y) + (a.z + a.w);
        q = (a.x * a.x + a.y * a.y) + (a.z * a.z + a.w * a.w);
    }
#pragma unroll
    for (int o = 16; o > 0; o >>= 1) {
        s += __shfl_down_sync(0xffffffffu, s, o);
        q += __shfl_down_sync(0xffffffffu, q, o);
    }
    __shared__ float ssw[AT / 32], sqw[AT / 32];
    int wid = threadIdx.x >> 5, lane = threadIdx.x & 31;
    if (lane == 0) { ssw[wid] = s; sqw[wid] = q; }
    __syncthreads();
    if (threadIdx.x == 0) {
        float ts = 0.f, tq = 0.f;
#pragma unroll
        for (int i = 0; i < AT / 32; i++) { ts += ssw[i]; tq += sqw[i]; }
        g_part[blockIdx.x] = make_float2(ts, tq);
    }
}

// ---- stage B: 64 blocks fold 32768 fp32 partials into 64 double pairs ----
__global__ void __launch_bounds__(256) reduceB(int nparts) {
    __shared__ double ss[256], sq[256];
    double s = 0.0, q = 0.0;
    for (int i = blockIdx.x * 256 + threadIdx.x; i < nparts; i += NB2 * 256) {
        float2 p = g_part[i];
        s += (double)p.x;
        q += (double)p.y;
    }
    ss[threadIdx.x] = s; sq[threadIdx.x] = q;
    __syncthreads();
    for (int o = 128; o > 0; o >>= 1) {
        if (threadIdx.x < o) {
            ss[threadIdx.x] += ss[threadIdx.x + o];
            sq[threadIdx.x] += sq[threadIdx.x + o];
        }
        __syncthreads();
    }
    if (threadIdx.x == 0) {
        g_mid[blockIdx.x] = ss[0];
        g_mid[NB2 + blockIdx.x] = sq[0];
    }
}

// ---- stage C: finalize mean/std (ddof=1) and fold constants ----
__global__ void reduceC(const float* __restrict__ alpha_p, long long n) {
    __shared__ double ss[NB2], sq[NB2];
    if (threadIdx.x < NB2) {
        ss[threadIdx.x] = g_mid[threadIdx.x];
        sq[threadIdx.x] = g_mid[NB2 + threadIdx.x];
    }
    __syncthreads();
    for (int o = NB2 / 2; o > 0; o >>= 1) {
        if (threadIdx.x < o) {
            ss[threadIdx.x] += ss[threadIdx.x + o];
            sq[threadIdx.x] += sq[threadIdx.x + o];
        }
        __syncthreads();
    }
    if (threadIdx.x == 0) {
        double N = (double)n;
        double mean = ss[0] / N;
        double var  = (sq[0] - N * mean * mean) / (N - 1.0);   // unbiased (ddof=1)
        double stdv = sqrt(var);
        double alpha = (double)(*alpha_p);
        double inv = 1.0 / (stdv * alpha);
        g_consts[0] = (float)inv;
        g_consts[1] = (float)(-mean * inv);
        g_consts[2] = (float)((double)(1.0f / 7.0f) * alpha);  // SF (fp32 1/7) * alpha
    }
}

// ---- quantize: one float4 per thread; 4-lane clusters own one group of 16 ----
__global__ void __launch_bounds__(QT) quant(const float4* __restrict__ xv,
                                            float4* __restrict__ ov,
                                            const int* __restrict__ ntp, int nvec) {
    // Reverse block order: consume the L2-resident tail left by reduceA first.
    int rb = gridDim.x - 1 - blockIdx.x;
    int idx = rb * blockDim.x + threadIdx.x;
    if (idx >= nvec) return;

    float scale = g_consts[0], bias = g_consts[1], C = g_consts[2];
    const float MAGIC = 8388608.0f;               // 2^23: RN add == round-half-even to int
    u64 s2 = pk2(scale, scale);
    u64 b2 = pk2(bias, bias);
    u64 seven2  = pk2(7.0f, 7.0f);
    u64 magic2  = pk2(MAGIC, MAGIC);
    u64 nmagic2 = pk2(-MAGIC, -MAGIC);
    u64 C2 = pk2(C, C);

    float4 v = xv[idx];                           // fully coalesced
    float X[4] = {v.x, v.y, v.z, v.w};

    float t[4], f[4];
#pragma unroll
    for (int p = 0; p < 2; p++) {
        u64 t2 = ffma2(pk2(X[2 * p], X[2 * p + 1]), s2, b2);    // t = x*scale + bias
        upk2(t2, t[2 * p], t[2 * p + 1]);
        float al = fminf(fabsf(t[2 * p]), 1.0f);                // |clip(t)| — FMNMX with |src|
        float ah = fminf(fabsf(t[2 * p + 1]), 1.0f);
        u64 f2 = ffma2(pk2(al, ah), seven2, magic2);            // f = 2^23 + q (round-half-even)
        upk2(f2, f[2 * p], f[2 * p + 1]);
    }

    // Group sum of q over the 16 elements owned by this 4-lane cluster.
    int qs = __float_as_int(f[0]) + __float_as_int(f[1]) +
             __float_as_int(f[2]) + __float_as_int(f[3]);
    qs += __shfl_xor_sync(0xffffffffu, qs, 1);
    qs += __shfl_xor_sync(0xffffffffu, qs, 2);

    int budget = __ldg(ntp) * 16;                 // num_terms * group_size

    float4 w;
    float* r = &w.x;
    // popc(q) <= (q+1)/2 for q in [0,7]  =>  sum(q) <= 2*budget-16 guarantees terms <= budget.
    if ((qs & 0xff) <= 2 * budget - 16) {
        // Fast path: every term kept -> qk == q.
#pragma unroll
        for (int p = 0; p < 2; p++) {
            u64 qf2 = fadd2(pk2(f[2 * p], f[2 * p + 1]), nmagic2);  // exact: qf = q as float
            u64 o2  = fmul2(qf2, C2);                               // |out| = q*SF*alpha
            float ol, oh; upk2(o2, ol, oh);
            r[2 * p]     = __int_as_float(__float_as_int(ol) | (__float_as_int(t[2 * p])     & 0x80000000));
            r[2 * p + 1] = __int_as_float(__float_as_int(oh) | (__float_as_int(t[2 * p + 1]) & 0x80000000));
        }
    } else {
        // Exact path (rare): stable-descending-sort semantics.
        int lane = threadIdx.x & 31;
        unsigned cmask = 0xFu << (lane & ~3);     // the 4 lanes of this cluster
        int pos = (lane & 3) * 4;                 // this lane's element offset in the group
        int m1 = 0, m2 = 0, m4 = 0;
#pragma unroll
        for (int k = 0; k < 4; k++) {
            int q = __float_as_int(f[k]) & 7;
            m1 |= (q & 1) << (pos + k);
            m2 |= ((q >> 1) & 1) << (pos + k);
            m4 |= ((q >> 2) & 1) << (pos + k);
        }
        m1 |= __shfl_xor_sync(cmask, m1, 1);  m1 |= __shfl_xor_sync(cmask, m1, 2);
        m2 |= __shfl_xor_sync(cmask, m2, 1);  m2 |= __shfl_xor_sync(cmask, m2, 2);
        m4 |= __shfl_xor_sync(cmask, m4, 1);  m4 |= __shfl_xor_sync(cmask, m4, 2);
        int c4 = min(__popc(m4), budget);
        int rem = budget - c4;
        int c2 = min(__popc(m2), rem); rem -= c2;
        int c1 = min(__popc(m1), rem);
        if (c1 < 0) c1 = 0;
#pragma unroll
        for (int k = 0; k < 4; k++) {
            int i16 = pos + k;
            int below = (1 << i16) - 1;
            int k4 = ((m4 >> i16) & 1) & ((__popc(m4 & below) < c4) ? 1 : 0);
            int k2 = ((m2 >> i16) & 1) & ((__popc(m2 & below) < c2) ? 1 : 0);
            int k1 = ((m1 >> i16) & 1) & ((__popc(m1 & below) < c1) ? 1 : 0);
            int kept = (k4 << 2) | (k2 << 1) | k1;
            float o = (float)kept * C;
            r[k] = __int_as_float(__float_as_int(o) | (__float_as_int(t[k]) & 0x80000000));
        }
    }

    stcs4(&ov[idx], w);                           // coalesced streaming store
}

extern "C" void kernel_launch(void* const* d_in, const int* in_sizes, int n_in,
                              void* d_out, int out_size) {
    const float* w     = (const float*)d_in[0];
    const float* alpha = (const float*)d_in[1];
    const int*   nt    = (const int*)d_in[2];
    int n = in_sizes[0];
    int nvec = n / 4;

    int na = (nvec + AT - 1) / AT;                // 32768 for 4096x8192
    if (na > MAXP) na = MAXP;                     // (holds for all realistic sizes)

    reduceA<<<na, AT>>>((const float4*)w, nvec);
    reduceB<<<NB2, 256>>>(na);
    reduceC<<<1, NB2>>>(alpha, (long long)n);
    int qb = (nvec + QT - 1) / QT;
    quant<<<qb, QT>>>((const float4*)w, (float4*)d_out, nt, nvec);
}